// round 16
// baseline (speedup 1.0000x reference)
#include <cuda_runtime.h>
#include <cuda_bf16.h>
#include <cuda_fp16.h>
#include <math.h>
#include <stdint.h>

// ---------------------------------------------------------------------------
// Problem constants
// ---------------------------------------------------------------------------
#define N_ROI   1000
#define M_PAD   1024
#define FH      38
#define FW      50
#define FCH     512
#define CROP    14
#define POOL    7
#define DFLAT   25088
#define DHID    4096
#define NCLS    21
#define NREG    80
#define NHEAD   128                 // padded head output width

#define WSCALE     1024.0f          // weight pre-scale (2^10)
#define INV_WSCALE (1.0f/1024.0f)

// prep mega-kernel block ranges
#define CW1_BLOCKS  (128 * 196)     // W1: (4096/32) x (25088/128) = 25088
#define CW2_BLOCKS  (128 * 32)      // W2: (4096/32) x (4096/128)  = 4096
#define CHD_BLOCKS  (128 * 16)      // head: 128 cols x 16 k-chunks = 2048
#define ROI_BLOCKS  (N_ROI * 4)     // 1000 rois x 4 py-pairs      = 4000
#define PREP_BLOCKS (CW1_BLOCKS + CW2_BLOCKS + CHD_BLOCKS + ROI_BLOCKS)

// ---------------------------------------------------------------------------
// Scratch (device globals — no allocation allowed)
// ---------------------------------------------------------------------------
__device__ __half g_x0 [(size_t)M_PAD * DFLAT];      // pooled feats, fp16
__device__ __half g_x1 [(size_t)M_PAD * DHID];       // FC1 out, fp16
__device__ __half g_x2 [(size_t)M_PAD * DHID];       // FC2 out, fp16
__device__ float  g_hd [(size_t)M_PAD * NHEAD];      // head GEMM out, fp32
__device__ __half g_w1 [(size_t)DHID * DFLAT];       // W1^T * 1024 fp16
__device__ __half g_w2 [(size_t)DHID * DHID];        // W2^T * 1024 fp16
__device__ __half g_whd[(size_t)NHEAD * DHID];       // [Wc|Wr|0]^T * 1024 fp16
__device__ float  g_bhd[NHEAD];                      // combined head bias

// ---------------------------------------------------------------------------
// asm helpers (compute_103-safe)
// ---------------------------------------------------------------------------
__device__ __forceinline__ uint32_t smem_u32(const void* p) {
    uint32_t a;
    asm("{ .reg .u64 t; cvta.to.shared.u64 t, %1; cvt.u32.u64 %0, t; }" : "=r"(a) : "l"(p));
    return a;
}
__device__ __forceinline__ void ldsm4(uint32_t r[4], uint32_t addr) {
    asm volatile("ldmatrix.sync.aligned.m8n8.x4.shared.b16 {%0,%1,%2,%3}, [%4];"
                 : "=r"(r[0]), "=r"(r[1]), "=r"(r[2]), "=r"(r[3]) : "r"(addr));
}
__device__ __forceinline__ void mma16816(float d[4], const uint32_t a[4],
                                         uint32_t b0, uint32_t b1) {
    asm volatile(
        "mma.sync.aligned.m16n8k16.row.col.f32.f16.f16.f32 "
        "{%0,%1,%2,%3}, {%4,%5,%6,%7}, {%8,%9}, {%0,%1,%2,%3};"
        : "+f"(d[0]), "+f"(d[1]), "+f"(d[2]), "+f"(d[3])
        : "r"(a[0]), "r"(a[1]), "r"(a[2]), "r"(a[3]), "r"(b0), "r"(b1));
}
#define CP_A16(dst, src) \
    asm volatile("cp.async.cg.shared.global [%0], [%1], 16;" :: "r"(dst), "l"(src))
#define CP_A16Z(dst, src, n) \
    asm volatile("cp.async.cg.shared.global [%0], [%1], 16, %2;" :: "r"(dst), "l"(src), "r"(n))
#define CP_COMMIT()      asm volatile("cp.async.commit_group;" ::: "memory")
#define CP_WAIT_GROUP(n) asm volatile("cp.async.wait_group %0;" :: "n"(n) : "memory")

__device__ __forceinline__ uint32_t pack2h(__half a, __half b) {
    __half2 t; t.x = a; t.y = b;
    return *(uint32_t*)&t;
}

// 64B-row swizzle: 16B chunk index XORed with (row>>1)&3. Conflict-free.
__device__ __forceinline__ uint32_t sw_off(int row, int chunk) {
    return (uint32_t)(row * 64 + ((chunk ^ ((row >> 1) & 3)) << 4));
}

// ---------------------------------------------------------------------------
// Prep mega-kernel: W1/W2/head conversions + ROI pool, one launch.
// Block ranges select the sub-task; 256 threads each.
// ---------------------------------------------------------------------------
__device__ void convert_w_body(const float* __restrict__ W,
                               __half* __restrict__ T,
                               int K, int N, int blk,
                               float ts[128][33])
{
    const int tx = threadIdx.x & 31;
    const int ty = threadIdx.x >> 5;       // 0..7
    const int nblk = blk & 127;            // N/32 = 128 always (N == 4096)
    const int kblk = blk >> 7;
    const int kb = kblk * 128;
    const int nb = nblk * 32;

    #pragma unroll
    for (int j = 0; j < 16; j++) {
        int r = ty + j * 8;                // 0..127
        ts[r][tx] = W[(size_t)(kb + r) * N + nb + tx];
    }
    __syncthreads();

    #pragma unroll
    for (int j = 0; j < 4; j++) {
        int n = ty + j * 8;                // 0..31
        float a0 = ts[4*tx + 0][n] * WSCALE;
        float a1 = ts[4*tx + 1][n] * WSCALE;
        float a2 = ts[4*tx + 2][n] * WSCALE;
        float a3 = ts[4*tx + 3][n] * WSCALE;
        size_t o = (size_t)(nb + n) * K + kb + 4 * tx;
        *(uint2*)&T[o] = make_uint2(
            pack2h(__float2half_rn(a0), __float2half_rn(a1)),
            pack2h(__float2half_rn(a2), __float2half_rn(a3)));
    }
}

__device__ void convert_head_body(const float* __restrict__ Wc, const float* __restrict__ bc,
                                  const float* __restrict__ Wr, const float* __restrict__ br,
                                  __half* __restrict__ T, float* __restrict__ bias,
                                  int blk)
{
    const int j  = blk & 127;                       // head col 0..127
    const int kb = blk >> 7;                        // 0..15
    const int k  = kb * 256 + threadIdx.x;          // 0..4095
    float v = 0.0f;
    if (j < NCLS)                 v = Wc[(size_t)k * NCLS + j];
    else if (j < NCLS + NREG)     v = Wr[(size_t)k * NREG + (j - NCLS)];
    T[(size_t)j * DHID + k] = __float2half_rn(v * WSCALE);

    if (kb == 0 && threadIdx.x == 0) {
        float bv = 0.0f;
        if (j < NCLS)             bv = bc[j];
        else if (j < NCLS + NREG) bv = br[j - NCLS];
        bias[j] = bv;
    }
}

__device__ void roi_body(const float* __restrict__ feats,
                         const float* __restrict__ props,
                         __half* __restrict__ x0, int blk)
{
    const int n    = blk >> 2;
    const int pair = blk & 3;
    const int half = threadIdx.x >> 7;       // 0/1
    const int py   = pair * 2 + half;
    const int c4   = threadIdx.x & 127;
    if (py >= POOL) return;

    const float y1 = props[n*4 + 0];
    const float x1 = props[n*4 + 1];
    const float y2 = props[n*4 + 2];
    const float x2 = props[n*4 + 3];

    const float Hm1 = (float)(FH - 1);
    const float Wm1 = (float)(FW - 1);
    const float ystep = (y2 - y1) * Hm1 * (1.0f / (CROP - 1));
    const float xstep = (x2 - x1) * Wm1 * (1.0f / (CROP - 1));
    const float ybase = y1 * Hm1;
    const float xbase = x1 * Wm1;

    int   y0i[2], y1i[2];
    float wy[2];
    #pragma unroll
    for (int dy = 0; dy < 2; dy++) {
        float ys = ybase + (float)(2*py + dy) * ystep;
        float yf = floorf(ys);
        wy[dy] = ys - yf;
        int yi = (int)yf;
        if (yi < 0) yi = 0;
        if (yi > FH-1) yi = FH-1;
        y0i[dy] = yi;
        y1i[dy] = (yi + 1 < FH-1) ? (yi + 1) : (FH-1);
    }

    for (int px = 0; px < POOL; px++) {
        float4 mx = make_float4(-1e30f, -1e30f, -1e30f, -1e30f);
        #pragma unroll
        for (int dx = 0; dx < 2; dx++) {
            float xs = xbase + (float)(2*px + dx) * xstep;
            float xf = floorf(xs);
            float wx = xs - xf;
            int xi = (int)xf;
            if (xi < 0) xi = 0;
            if (xi > FW-1) xi = FW-1;
            int x0c = xi;
            int x1c = (xi + 1 < FW-1) ? (xi + 1) : (FW-1);
            #pragma unroll
            for (int dy = 0; dy < 2; dy++) {
                const float4* r0 = (const float4*)&feats[((size_t)y0i[dy]*FW)*FCH];
                const float4* r1 = (const float4*)&feats[((size_t)y1i[dy]*FW)*FCH];
                float4 v00 = r0[(size_t)x0c*(FCH/4) + c4];
                float4 v01 = r0[(size_t)x1c*(FCH/4) + c4];
                float4 v10 = r1[(size_t)x0c*(FCH/4) + c4];
                float4 v11 = r1[(size_t)x1c*(FCH/4) + c4];
                float w = wy[dy];
                float4 top, bot, val;
                top.x = v00.x + (v01.x - v00.x) * wx;
                top.y = v00.y + (v01.y - v00.y) * wx;
                top.z = v00.z + (v01.z - v00.z) * wx;
                top.w = v00.w + (v01.w - v00.w) * wx;
                bot.x = v10.x + (v11.x - v10.x) * wx;
                bot.y = v10.y + (v11.y - v10.y) * wx;
                bot.z = v10.z + (v11.z - v10.z) * wx;
                bot.w = v10.w + (v11.w - v10.w) * wx;
                val.x = top.x + (bot.x - top.x) * w;
                val.y = top.y + (bot.y - top.y) * w;
                val.z = top.z + (bot.z - top.z) * w;
                val.w = top.w + (bot.w - top.w) * w;
                mx.x = fmaxf(mx.x, val.x);
                mx.y = fmaxf(mx.y, val.y);
                mx.z = fmaxf(mx.z, val.z);
                mx.w = fmaxf(mx.w, val.w);
            }
        }
        size_t idx = (size_t)n*DFLAT + ((size_t)(py*POOL + px))*FCH + (size_t)c4*4;
        *(uint2*)&x0[idx] = make_uint2(
            pack2h(__float2half_rn(mx.x), __float2half_rn(mx.y)),
            pack2h(__float2half_rn(mx.z), __float2half_rn(mx.w)));
    }
}

__global__ __launch_bounds__(256)
void prep_kernel(const float* __restrict__ feats,
                 const float* __restrict__ props,
                 const float* __restrict__ W1,
                 const float* __restrict__ W2,
                 const float* __restrict__ Wc, const float* __restrict__ bc,
                 const float* __restrict__ Wr, const float* __restrict__ br,
                 __half* __restrict__ x0,
                 __half* __restrict__ w1, __half* __restrict__ w2,
                 __half* __restrict__ whd, float* __restrict__ bhd)
{
    __shared__ float ts[128][33];
    const int b = blockIdx.x;
    if (b < CW1_BLOCKS) {
        convert_w_body(W1, w1, DFLAT, DHID, b, ts);
    } else if (b < CW1_BLOCKS + CW2_BLOCKS) {
        convert_w_body(W2, w2, DHID, DHID, b - CW1_BLOCKS, ts);
    } else if (b < CW1_BLOCKS + CW2_BLOCKS + CHD_BLOCKS) {
        convert_head_body(Wc, bc, Wr, br, whd, bhd, b - CW1_BLOCKS - CW2_BLOCKS);
    } else {
        roi_body(feats, props, x0, b - CW1_BLOCKS - CW2_BLOCKS - CHD_BLOCKS);
    }
}

// ---------------------------------------------------------------------------
// HMMA fp16 single-product GEMM.
// D = act((A @ B^T) * 2^-10 + bias); A fp16, B = W^T*1024 fp16.
// BM=128, BN=128, BK=32, 256 threads, warp tile 64x32, 6-stage cp.async,
// 64B swizzled rows, 2 CTAs/SM.
// ---------------------------------------------------------------------------
#define A_S 0
#define B_S 8192
#define STAGE  16384
#define NSTAGE 6
#define GEMM_SMEM (NSTAGE * STAGE)     // 98304 B -> 2 CTAs/SM

__global__ __launch_bounds__(256, 2)
void gemm_tc_kernel(const __half* __restrict__ A,
                    int m_real,
                    const __half* __restrict__ B,
                    const float* __restrict__ bias,
                    float* __restrict__ Cf,
                    __half* __restrict__ Chf,
                    int K, int ldc, int out_f16, int do_relu)
{
    extern __shared__ char smem[];
    const uint32_t sb0 = smem_u32(smem);
    const int tid  = threadIdx.x;
    const int wid  = tid >> 5;
    const int lane = tid & 31;
    const int wm   = wid & 1;            // 0..1 (M groups of 64)
    const int wn   = wid >> 1;           // 0..3 (N groups of 32)
    const int bn = blockIdx.x, bm = blockIdx.y;
    const int nch = K >> 5;

    // ---- load roles: rows lr and lr+64, 16B chunk lc ----
    const int lr = tid >> 2;             // 0..63
    const int lc = tid & 3;
    uint32_t a_fill[2]; const __half *as[2], *bs[2];
    uint32_t dofs[2];
    #pragma unroll
    for (int p = 0; p < 2; p++) {
        int row = lr + p * 64;
        int gm  = bm * 128 + row;
        a_fill[p] = (gm < m_real) ? 16u : 0u;
        int sr = (gm < m_real) ? gm : (m_real - 1);
        as[p] = A + (size_t)sr * K + lc * 8;
        bs[p] = B + (size_t)(bn * 128 + row) * K + lc * 8;
        dofs[p] = sw_off(row, lc);
    }

    float acc[4][4][4];
    #pragma unroll
    for (int i = 0; i < 4; i++)
        #pragma unroll
        for (int j = 0; j < 4; j++)
            #pragma unroll
            for (int e = 0; e < 4; e++) acc[i][j][e] = 0.0f;

    // ---- prologue: stages 0..4 ----
    #pragma unroll
    for (int s = 0; s < 5; s++) {
        if (s < nch) {
            const uint32_t st = sb0 + (uint32_t)s * STAGE;
            const int k0 = s * 32;
            #pragma unroll
            for (int p = 0; p < 2; p++) {
                CP_A16Z(st + A_S + dofs[p], as[p] + k0, a_fill[p]);
                CP_A16(st + B_S + dofs[p], bs[p] + k0);
            }
        }
        CP_COMMIT();
    }

    for (int c = 0; c < nch; c++) {
        const uint32_t st = sb0 + (uint32_t)(c % NSTAGE) * STAGE;
        CP_WAIT_GROUP(4);
        __syncthreads();

        if (c + 5 < nch) {
            const uint32_t sn = sb0 + (uint32_t)((c + 5) % NSTAGE) * STAGE;
            const int k0 = (c + 5) * 32;
            #pragma unroll
            for (int p = 0; p < 2; p++) {
                CP_A16Z(sn + A_S + dofs[p], as[p] + k0, a_fill[p]);
                CP_A16(sn + B_S + dofs[p], bs[p] + k0);
            }
        }
        CP_COMMIT();

        #pragma unroll
        for (int kk = 0; kk < 2; kk++) {
            const int chunk = kk * 2 + (lane >> 4);
            const int lrow  = lane & 15;
            uint32_t q[2][4];
            #pragma unroll
            for (int nt2 = 0; nt2 < 2; nt2++) {
                int r = wn*32 + nt2*16 + lrow;
                ldsm4(q[nt2], st + B_S + sw_off(r, chunk));
            }
            uint32_t a4[4][4];
            #pragma unroll
            for (int mt = 0; mt < 4; mt++) {
                int r = wm*64 + mt*16 + lrow;
                ldsm4(a4[mt], st + A_S + sw_off(r, chunk));
            }
            #pragma unroll
            for (int mt = 0; mt < 4; mt++)
                #pragma unroll
                for (int nt2 = 0; nt2 < 2; nt2++) {
                    mma16816(acc[mt][2*nt2],   a4[mt], q[nt2][0], q[nt2][2]);
                    mma16816(acc[mt][2*nt2+1], a4[mt], q[nt2][1], q[nt2][3]);
                }
        }
    }

    // ---- epilogue: descale + bias (+relu) ----
    #pragma unroll
    for (int mt = 0; mt < 4; mt++) {
        const int row0 = bm*128 + wm*64 + mt*16 + (lane >> 2);
        #pragma unroll
        for (int nt = 0; nt < 4; nt++) {
            const int gn = bn*128 + wn*32 + nt*8 + 2*(lane & 3);
            const float b0 = bias[gn], b1 = bias[gn+1];
            float v00 = fmaf(acc[mt][nt][0], INV_WSCALE, b0);
            float v01 = fmaf(acc[mt][nt][1], INV_WSCALE, b1);
            float v10 = fmaf(acc[mt][nt][2], INV_WSCALE, b0);
            float v11 = fmaf(acc[mt][nt][3], INV_WSCALE, b1);
            if (do_relu) {
                v00 = fmaxf(v00, 0.f); v01 = fmaxf(v01, 0.f);
                v10 = fmaxf(v10, 0.f); v11 = fmaxf(v11, 0.f);
            }
            if (out_f16) {
                *(uint32_t*)&Chf[(size_t)row0 * ldc + gn] =
                    pack2h(__float2half_rn(v00), __float2half_rn(v01));
                *(uint32_t*)&Chf[(size_t)(row0+8) * ldc + gn] =
                    pack2h(__float2half_rn(v10), __float2half_rn(v11));
            } else {
                *(float2*)&Cf[(size_t)row0 * ldc + gn]     = make_float2(v00, v01);
                *(float2*)&Cf[(size_t)(row0+8) * ldc + gn] = make_float2(v10, v11);
            }
        }
    }
}

// ---------------------------------------------------------------------------
// Head postprocess — softmax(cls) + copy(reg). 1 thread per ROI.
// ---------------------------------------------------------------------------
__global__ __launch_bounds__(128)
void head_post_kernel(const float* __restrict__ hd, float* __restrict__ out)
{
    const int r = blockIdx.x * 128 + threadIdx.x;
    if (r >= N_ROI) return;
    const float* row = hd + (size_t)r * NHEAD;

    float m = row[0];
    #pragma unroll
    for (int j = 1; j < NCLS; j++) m = fmaxf(m, row[j]);
    float e[NCLS], s = 0.f;
    #pragma unroll
    for (int j = 0; j < NCLS; j++) { e[j] = expf(row[j] - m); s += e[j]; }
    float inv = 1.0f / s;
    #pragma unroll
    for (int j = 0; j < NCLS; j++) out[(size_t)r * NCLS + j] = e[j] * inv;

    #pragma unroll
    for (int j = 0; j < NREG; j++)
        out[(size_t)N_ROI * NCLS + (size_t)r * NREG + j] = row[NCLS + j];
}

// ---------------------------------------------------------------------------
// Launch
// ---------------------------------------------------------------------------
extern "C" void kernel_launch(void* const* d_in, const int* in_sizes, int n_in,
                              void* d_out, int out_size)
{
    const float* feats = (const float*)d_in[0];
    const float* props = (const float*)d_in[1];
    const float* W1    = (const float*)d_in[2];
    const float* b1    = (const float*)d_in[3];
    const float* W2    = (const float*)d_in[4];
    const float* b2    = (const float*)d_in[5];
    const float* Wc    = (const float*)d_in[6];
    const float* bc    = (const float*)d_in[7];
    const float* Wr    = (const float*)d_in[8];
    const float* br    = (const float*)d_in[9];
    float* out = (float*)d_out;

    __half *x0, *x1, *x2, *w1, *w2, *whd;
    float *hd, *bhd;
    cudaGetSymbolAddress((void**)&x0,  g_x0);
    cudaGetSymbolAddress((void**)&x1,  g_x1);
    cudaGetSymbolAddress((void**)&x2,  g_x2);
    cudaGetSymbolAddress((void**)&hd,  g_hd);
    cudaGetSymbolAddress((void**)&w1,  g_w1);
    cudaGetSymbolAddress((void**)&w2,  g_w2);
    cudaGetSymbolAddress((void**)&whd, g_whd);
    cudaGetSymbolAddress((void**)&bhd, g_bhd);

    cudaFuncSetAttribute(gemm_tc_kernel, cudaFuncAttributeMaxDynamicSharedMemorySize, GEMM_SMEM);

    // 1. Fused prep: roi+pool -> x0, W1/W2/head weight conversion (one launch)
    prep_kernel<<<PREP_BLOCKS, 256>>>(feats, props, W1, W2, Wc, bc, Wr, br,
                                      x0, w1, w2, whd, bhd);

    // 2. FC1 -> x1 fp16 (relu)
    gemm_tc_kernel<<<dim3(DHID / 128, M_PAD / 128), 256, GEMM_SMEM>>>(
        x0, N_ROI, w1, b1, nullptr, x1, DFLAT, DHID, 1, 1);

    // 3. FC2 -> x2 fp16 (relu)
    gemm_tc_kernel<<<dim3(DHID / 128, M_PAD / 128), 256, GEMM_SMEM>>>(
        x1, M_PAD, w2, b2, nullptr, x2, DHID, DHID, 1, 1);

    // 4. Head GEMM -> hd fp32 [1024 x 128] (no relu)
    gemm_tc_kernel<<<dim3(1, M_PAD / 128), 256, GEMM_SMEM>>>(
        x2, M_PAD, whd, bhd, hd, nullptr, DHID, NHEAD, 0, 0);

    // 5. Softmax + scatter
    head_post_kernel<<<(N_ROI + 127) / 128, 128>>>(hd, out);
}